// round 5
// baseline (speedup 1.0000x reference)
#include <cuda_runtime.h>
#include <math.h>

#define TT 20
#define MM 2000
#define NROWS (TT*MM)          // 40000, row index = t*MM + m
#define CAP 96

#define FMA2(d,a,b) asm("fma.rn.f32x2 %0,%1,%2,%0;" : "+l"(d) : "l"(a), "l"(b))
#define UNPK(lo,hi,v) asm("mov.b64 {%0,%1},%2;" : "=f"(lo), "=f"(hi) : "l"(v))

// ---------------- static scratch ----------------
__device__ float          d_maskf[NROWS];
__device__ int            d_cnt[NROWS];
__device__ float          d_dinv[NROWS];
__device__ unsigned short d_nbr[(size_t)NROWS * CAP];
__device__ float          d_bufA[(size_t)NROWS * 128];   // Z1 / Z2
__device__ float          d_bufB[(size_t)NROWS * 128];   // h1 / placeholder
__device__ float          d_gpre[(size_t)NROWS * 512];   // [m*T+t][512]
__device__ float          d_lstm[(size_t)NROWS * 128];   // [m*T+t][128]

__device__ __forceinline__ float sigm(float x) { return 1.0f / (1.0f + expf(-x)); }

// ---------------- mbarrier / cluster helpers ----------------
__device__ __forceinline__ unsigned smem_u32(const void* p) {
    unsigned a;
    asm("{ .reg .u64 t; cvta.to.shared.u64 t, %1; cvt.u32.u64 %0, t; }" : "=r"(a) : "l"(p));
    return a;
}
__device__ __forceinline__ unsigned mapa_peer(unsigned local, unsigned peer_rank) {
    unsigned r;
    asm("mapa.shared::cluster.u32 %0, %1, %2;" : "=r"(r) : "r"(local), "r"(peer_rank));
    return r;
}
__device__ __forceinline__ void mbar_init(unsigned a, unsigned cnt) {
    asm volatile("mbarrier.init.shared.b64 [%0], %1;" :: "r"(a), "r"(cnt) : "memory");
}
__device__ __forceinline__ void mbar_expect_tx(unsigned a, unsigned bytes) {
    asm volatile("mbarrier.arrive.expect_tx.shared.b64 _, [%0], %1;" :: "r"(a), "r"(bytes) : "memory");
}
__device__ __forceinline__ void mbar_arrive_remote(unsigned remote) {
    asm volatile("mbarrier.arrive.shared::cluster.b64 _, [%0];" :: "r"(remote) : "memory");
}
__device__ __forceinline__ void st_async_f32(unsigned remote_addr, float v, unsigned remote_mbar) {
    asm volatile("st.async.shared::cluster.mbarrier::complete_tx::bytes.b32 [%0], %1, [%2];"
                 :: "r"(remote_addr), "r"(__float_as_uint(v)), "r"(remote_mbar) : "memory");
}
__device__ __forceinline__ void mbar_wait(unsigned a, unsigned parity) {
    asm volatile(
        "{\n\t.reg .pred P;\n\t"
        "LW_%=:\n\t"
        "mbarrier.try_wait.parity.acquire.cluster.shared::cta.b64 P, [%0], %1, 0x989680;\n\t"
        "@P bra.uni LD_%=;\n\t"
        "bra.uni LW_%=;\n\t"
        "LD_%=:\n\t}"
        :: "r"(a), "r"(parity) : "memory");
}
#define CLUSTER_SYNC_() do { \
    asm volatile("barrier.cluster.arrive.aligned;" ::: "memory"); \
    asm volatile("barrier.cluster.wait.aligned;" ::: "memory"); } while (0)

// ---------------- mask init ----------------
__global__ void k_init(const unsigned int* __restrict__ em) {
    int idx = blockIdx.x * 256 + threadIdx.x;
    if (idx >= NROWS) return;
    int t = idx / MM, i = idx % MM;
    int b = i / 500, n = i % 500;
    d_maskf[idx] = em[(b * TT + t) * 500 + n] ? 1.0f : 0.0f;
}

// ---------------- column-scan sparse extraction (atomic-free, deterministic) ----------------
__global__ void k_extract(const float* __restrict__ adj) {
    int t = blockIdx.y;
    int i = blockIdx.x * 256 + threadIdx.x;
    __shared__ float msm[MM];
    for (int j = threadIdx.x; j < MM; j += 256) msm[j] = d_maskf[t * MM + j];
    __syncthreads();
    if (i >= MM) return;
    const float* a = adj + (size_t)t * MM * MM + i;   // column i
    unsigned short* list = d_nbr + (size_t)(t * MM + i) * CAP;
    int cnt = 0;
    #pragma unroll 8
    for (int j = 0; j < MM; j++) {
        float av = a[(size_t)j * MM];
        if (av != 0.0f && msm[j] != 0.0f) {
            if (cnt < CAP) list[cnt] = (unsigned short)j;
            cnt++;
        }
    }
    float mi = d_maskf[t * MM + i];
    d_cnt[t * MM + i] = (cnt < CAP ? cnt : CAP);
    d_dinv[t * MM + i] = (mi != 0.0f) ? rsqrtf((float)cnt + 1.0f) : 0.0f;
}

// ---------------- Z1 = dinv .* (x @ W1) ----------------
__global__ void k_z1(const float* __restrict__ pos, const float* __restrict__ W1) {
    int idx = blockIdx.x * 256 + threadIdx.x;
    if (idx >= NROWS * 128) return;
    int row = idx >> 7, c = idx & 127;
    float x0 = __ldg(&pos[(size_t)row * 2]);
    float x1 = __ldg(&pos[(size_t)row * 2 + 1]);
    d_bufA[idx] = d_dinv[row] * (x0 * __ldg(&W1[c]) + x1 * __ldg(&W1[128 + c]));
}

// ---------------- aggregation: out[i] = f( dinv[i]*(sum_nbr Z[j] + Z[i]) + bias ) ----------------
__global__ void k_agg(const float* __restrict__ Zin, const float* __restrict__ bias,
                      float* __restrict__ out, int mode) {
    int row = blockIdx.x;
    int f = threadIdx.x;
    int t = row / MM;
    size_t base = (size_t)t * MM;
    float acc = Zin[(size_t)row * 128 + f];
    int n = d_cnt[row];
    const unsigned short* lst = &d_nbr[(size_t)row * CAP];
    for (int idx = 0; idx < n; idx++) {
        int j = lst[idx];
        acc += Zin[(base + j) * 128 + f];
    }
    float v = d_dinv[row] * acc + __ldg(&bias[f]);
    if (mode == 0) out[(size_t)row * 128 + f] = fmaxf(v, 0.0f);
    else           out[(size_t)row * 128 + f] = v * d_maskf[row];
}

// ---------------- tiled GEMM, K=128 fixed, packed f32x2 ----------------
// mode 0 (Z2):    A row = r,                B = W2   [k][c],  epi: *dinv[r]
// mode 1 (gates): A row = (r%20)*2000+r/20, B = W_ih [c][k],  epi: + b_ih[c]+b_hh[c]
__global__ void __launch_bounds__(256)
k_gemm(const float* __restrict__ A, const float* __restrict__ B, float* __restrict__ C,
       const float* __restrict__ bia, const float* __restrict__ bib,
       int mode, int ncols) {
    extern __shared__ float sm[];
    float* As = sm;            // [64][128]
    float* Bs = sm + 64 * 128; // [128][130]
    int r0 = blockIdx.x * 64, c0 = blockIdx.y * 128;
    int tid = threadIdx.x;

    for (int i = tid; i < 64 * 32; i += 256) {
        int row = i / 32, k4 = i % 32;
        int gr = r0 + row;
        int arow = (mode == 1) ? ((gr % TT) * MM + gr / TT) : gr;
        ((float4*)As)[row * 32 + k4] = ((const float4*)A)[(size_t)arow * 32 + k4];
    }
    if (mode == 1) {
        for (int i = tid; i < 128 * 32; i += 256) {
            int c = i / 32, k4 = i % 32;
            float4 v = ((const float4*)B)[(size_t)(c0 + c) * 32 + k4];
            Bs[c * 130 + 4 * k4 + 0] = v.x; Bs[c * 130 + 4 * k4 + 1] = v.y;
            Bs[c * 130 + 4 * k4 + 2] = v.z; Bs[c * 130 + 4 * k4 + 3] = v.w;
        }
    } else {
        for (int i = tid; i < 128 * 32; i += 256) {
            int k = i / 32, c4 = i % 32;
            float4 v = ((const float4*)B)[(size_t)k * 32 + c4];
            Bs[(4 * c4 + 0) * 130 + k] = v.x; Bs[(4 * c4 + 1) * 130 + k] = v.y;
            Bs[(4 * c4 + 2) * 130 + k] = v.z; Bs[(4 * c4 + 3) * 130 + k] = v.w;
        }
    }
    __syncthreads();

    int tx = tid % 32, ty = tid / 32;
    unsigned long long acc[8][4];
    #pragma unroll
    for (int rr = 0; rr < 8; rr++)
        #pragma unroll
        for (int cc = 0; cc < 4; cc++) acc[rr][cc] = 0ull;

    const ulonglong2* As2 = (const ulonglong2*)As;
    #pragma unroll 4
    for (int k4 = 0; k4 < 32; k4++) {
        ulonglong2 a[8];
        #pragma unroll
        for (int rr = 0; rr < 8; rr++) a[rr] = As2[(ty * 8 + rr) * 32 + k4];
        #pragma unroll
        for (int cc = 0; cc < 4; cc++) {
            int c = tx + 32 * cc;
            const unsigned long long* bp = (const unsigned long long*)(Bs + c * 130 + 4 * k4);
            unsigned long long b0 = bp[0], b1 = bp[1];
            #pragma unroll
            for (int rr = 0; rr < 8; rr++) {
                FMA2(acc[rr][cc], a[rr].x, b0);
                FMA2(acc[rr][cc], a[rr].y, b1);
            }
        }
    }
    #pragma unroll
    for (int cc = 0; cc < 4; cc++) {
        int c = tx + 32 * cc;
        float bv = (mode == 1) ? (__ldg(&bia[c0 + c]) + __ldg(&bib[c0 + c])) : 0.0f;
        #pragma unroll
        for (int rr = 0; rr < 8; rr++) {
            int r = r0 + ty * 8 + rr;
            float lo, hi; UNPK(lo, hi, acc[rr][cc]);
            float v = lo + hi;
            if (mode == 1) v += bv;
            else           v *= d_dinv[r];
            C[(size_t)r * ncols + c0 + c] = v;
        }
    }
}

// ---------------- cluster LSTM: 2 CTAs per t-row, k-split by half ----------------
// CTA r thread g holds W_hh[g][64r:64r+64] in 32 ull registers (whole W_hh in 2 RFs).
// Each CTA computes h[64r:64r+64] -> its own dot input; only 256 gate-partials/step
// cross the cluster (st.async, double-buffered, mbarrier full/empty credits).
__global__ void __launch_bounds__(512, 1) __cluster_dims__(2, 1, 1)
k_lstm2(const float* __restrict__ Whh) {
    __shared__ float hs[64];
    __shared__ float gsm[512];
    __shared__ float psm[1024];                            // [2][512]
    __shared__ float nsm[256];                             // [quad][64]
    __shared__ __align__(8) unsigned long long mbars[4];   // full0 full1 empty0 empty1

    unsigned rank = blockIdx.x & 1;
    int t = blockIdx.x >> 1;
    int g = threadIdx.x;
    unsigned peer = rank ^ 1u;

    unsigned barsA = smem_u32(mbars);
    unsigned fullA[2]  = { barsA,      barsA + 8  };
    unsigned emptyA[2] = { barsA + 16, barsA + 24 };
    unsigned psmA = smem_u32(psm);
    unsigned p_full[2]  = { mapa_peer(fullA[0], peer),  mapa_peer(fullA[1], peer)  };
    unsigned p_empty[2] = { mapa_peer(emptyA[0], peer), mapa_peer(emptyA[1], peer) };
    unsigned p_psm = mapa_peer(psmA, peer);

    if (g == 0) {
        mbar_init(fullA[0], 1); mbar_init(fullA[1], 1);
        mbar_init(emptyA[0], 1); mbar_init(emptyA[1], 1);
    }
    if (g < 64) hs[g] = 0.0f;

    unsigned long long w[32];
    const unsigned long long* wrow = (const unsigned long long*)(Whh + (size_t)g * 128 + 64 * rank);
    #pragma unroll
    for (int i = 0; i < 32; i++) w[i] = wrow[i];

    __syncthreads();
    CLUSTER_SYNC_();   // mbarriers visible cluster-wide before any st.async

    // warp-uniform: bit6 of g selects the h-half owner
    bool mine = (((g >> 6) & 1) == (int)rank);
    float c = 0.0f;
    float gpv = (rank == 0) ? d_gpre[(size_t)t * 512 + g] : 0.0f;
    int fph0 = 0, fph1 = 0, eph0 = 1, eph1 = 1;

    for (int m = 0; m < MM; m++) {
        int s = m & 1;
        unsigned fa = fullA[s], ea = emptyA[s];
        int fp = s ? fph1 : fph0;
        int ep = s ? eph1 : eph0;

        // dot over my 64-k slice (weights fully in registers, h broadcast from smem)
        unsigned long long acc = 0ull;
        const ulonglong2* h2 = (const ulonglong2*)hs;
        #pragma unroll
        for (int j = 0; j < 16; j++) {
            ulonglong2 hv = h2[j];
            FMA2(acc, hv.x, w[2 * j]);
            FMA2(acc, hv.y, w[2 * j + 1]);
        }
        float lo, hi; UNPK(lo, hi, acc);
        float part = lo + hi + gpv;
        float gnew = 0.0f;
        if (rank == 0 && m < MM - 1) gnew = d_gpre[(size_t)((m + 1) * TT + t) * 512 + g];

        if (g == 0) mbar_expect_tx(fa, 1024u);
        gsm[g] = part;
        if (!mine) {                                  // 8 whole warps: send partial to peer
            mbar_wait(ea, (unsigned)ep);              // credit from peer's m-2 consume
            st_async_f32(p_psm + (unsigned)(s * 2048 + g * 4), part, p_full[s]);
        }
        __syncthreads();

        if (mine) {                                   // 8 whole warps: gate nonlinearity
            mbar_wait(fa, (unsigned)fp);
            float v = gsm[g] + psm[s * 512 + g];
            int quad = g >> 7, j = g & 63;
            float r = (quad == 2) ? tanhf(v) : sigm(v);
            nsm[quad * 64 + j] = r;
        }
        __syncthreads();

        if (g == 0) mbar_arrive_remote(p_empty[s]);   // psm[s] consumed -> peer credit
        if (g < 64) {
            float ig = nsm[g], fg = nsm[64 + g], gg = nsm[128 + g], og = nsm[192 + g];
            c = fg * c + ig * gg;
            float hn = og * tanhf(c);
            hs[g] = hn;
            d_lstm[(size_t)(m * TT + t) * 128 + 64 * rank + g] = hn;
        }
        gpv = gnew;
        if (s) { fph1 ^= 1; eph1 ^= 1; } else { fph0 ^= 1; eph0 ^= 1; }
        __syncthreads();
    }

    CLUSTER_SYNC_();   // no CTA exits while peer ops may target its smem
}

// ---------------- fused FC1(relu)+FC2, 64 rows/block, packed f32x2 ----------------
__global__ void __launch_bounds__(256)
k_fc(const float* __restrict__ fc1w, const float* __restrict__ fc1b,
     const float* __restrict__ fc2w, const float* __restrict__ fc2b,
     float* __restrict__ out) {
    extern __shared__ float sm[];
    float* w1t = sm;                   // [64][130]
    float* w2t = w1t + 64 * 130;       // [32][66]
    float* xs  = w2t + 32 * 66;        // [64][128]
    float* mid = xs  + 64 * 128;       // [64][66]
    int tid = threadIdx.x;

    for (int i = tid; i < 128 * 64; i += 256) {
        int k = i >> 6, cc = i & 63;
        w1t[cc * 130 + k] = fc1w[i];
    }
    for (int i = tid; i < 64 * 32; i += 256) {
        int k = i >> 5, o = i & 31;
        w2t[o * 66 + k] = fc2w[i];
    }
    int rbase = blockIdx.x * 64;
    for (int i = tid; i < 64 * 32; i += 256)
        ((float4*)xs)[i] = ((const float4*)d_lstm)[(size_t)rbase * 32 + i];
    __syncthreads();

    int r = tid >> 2, q = tid & 3;
    {
        unsigned long long acc[16];
        #pragma unroll
        for (int j = 0; j < 16; j++) acc[j] = 0ull;
        const unsigned long long* xr = (const unsigned long long*)(xs + r * 128);
        #pragma unroll 4
        for (int kp = 0; kp < 64; kp++) {
            unsigned long long xv = xr[kp];
            #pragma unroll
            for (int j = 0; j < 16; j++)
                FMA2(acc[j], xv, *(const unsigned long long*)(w1t + (q * 16 + j) * 130 + 2 * kp));
        }
        #pragma unroll
        for (int j = 0; j < 16; j++) {
            float lo, hi; UNPK(lo, hi, acc[j]);
            int cc = q * 16 + j;
            mid[r * 66 + cc] = fmaxf(lo + hi + __ldg(&fc1b[cc]), 0.0f);
        }
    }
    __syncthreads();
    {
        unsigned long long acc[8];
        #pragma unroll
        for (int j = 0; j < 8; j++) acc[j] = 0ull;
        const unsigned long long* mr = (const unsigned long long*)(mid + r * 66);
        #pragma unroll 4
        for (int kp = 0; kp < 32; kp++) {
            unsigned long long mv = mr[kp];
            #pragma unroll
            for (int j = 0; j < 8; j++)
                FMA2(acc[j], mv, *(const unsigned long long*)(w2t + (q * 8 + j) * 66 + 2 * kp));
        }
        #pragma unroll
        for (int j = 0; j < 8; j++) {
            float lo, hi; UNPK(lo, hi, acc[j]);
            int o = q * 8 + j;
            out[(size_t)(rbase + r) * 32 + o] = lo + hi + __ldg(&fc2b[o]);
        }
    }
}

// ---------------- launch ----------------
extern "C" void kernel_launch(void* const* d_in, const int* in_sizes, int n_in,
                              void* d_out, int out_size) {
    const float* positions = (const float*)d_in[0];
    const float* adjacency = (const float*)d_in[1];
    const unsigned int* ego = (const unsigned int*)d_in[2];
    const float* W1   = (const float*)d_in[3];
    const float* b1   = (const float*)d_in[4];
    const float* W2   = (const float*)d_in[5];
    const float* b2   = (const float*)d_in[6];
    const float* W_ih = (const float*)d_in[7];
    const float* W_hh = (const float*)d_in[8];
    const float* b_ih = (const float*)d_in[9];
    const float* b_hh = (const float*)d_in[10];
    const float* fc1w = (const float*)d_in[11];
    const float* fc1b = (const float*)d_in[12];
    const float* fc2w = (const float*)d_in[13];
    const float* fc2b = (const float*)d_in[14];
    float* out = (float*)d_out;

    static const int GEMM_SMEM = (64 * 128 + 128 * 130) * 4;
    static const int FC_SMEM   = (64 * 130 + 32 * 66 + 64 * 128 + 64 * 66) * 4;
    cudaFuncSetAttribute(k_gemm, cudaFuncAttributeMaxDynamicSharedMemorySize, GEMM_SMEM);
    cudaFuncSetAttribute(k_fc,   cudaFuncAttributeMaxDynamicSharedMemorySize, FC_SMEM);

    float* bufA; cudaGetSymbolAddress((void**)&bufA, d_bufA);
    float* bufB; cudaGetSymbolAddress((void**)&bufB, d_bufB);
    float* gpre; cudaGetSymbolAddress((void**)&gpre, d_gpre);

    k_init<<<(NROWS + 255) / 256, 256>>>(ego);
    k_extract<<<dim3(8, TT), 256>>>(adjacency);
    k_z1<<<(NROWS * 128 + 255) / 256, 256>>>(positions, W1);
    k_agg<<<NROWS, 128>>>(bufA, b1, bufB, 0);                                   // h1
    k_gemm<<<dim3(625, 1), 256, GEMM_SMEM>>>(bufB, W2, bufA, 0, 0, 0, 128);     // Z2
    k_agg<<<NROWS, 128>>>(bufA, b2, bufB, 1);                                   // placeholder
    k_gemm<<<dim3(625, 4), 256, GEMM_SMEM>>>(bufB, W_ih, gpre, b_ih, b_hh, 1, 512);
    k_lstm2<<<2 * TT, 512>>>(W_hh);
    k_fc<<<625, 256, FC_SMEM>>>(fc1w, fc1b, fc2w, fc2b, out);
}

// round 6
// speedup vs baseline: 1.1355x; 1.1355x over previous
#include <cuda_runtime.h>
#include <math.h>

#define TT 20
#define MM 2000
#define NROWS (TT*MM)          // 40000, row index = t*MM + m
#define CAP 96

#define FMA2(d,a,b) asm("fma.rn.f32x2 %0,%1,%2,%0;" : "+l"(d) : "l"(a), "l"(b))
#define UNPK(lo,hi,v) asm("mov.b64 {%0,%1},%2;" : "=f"(lo), "=f"(hi) : "l"(v))

// ---------------- static scratch ----------------
__device__ float          d_maskf[NROWS];
__device__ int            d_cnt[NROWS];
__device__ float          d_dinv[NROWS];
__device__ unsigned short d_nbr[(size_t)NROWS * CAP];
__device__ float          d_bufA[(size_t)NROWS * 128];   // Z1 / Z2
__device__ float          d_bufB[(size_t)NROWS * 128];   // h1 / placeholder
__device__ float          d_gpre[(size_t)NROWS * 512];   // [m*T+t][512]
__device__ float          d_lstm[(size_t)NROWS * 128];   // [m*T+t][128]

// fast nonlinearities: MUFU EX2 based, err ~1e-7 (vs 1e-3 tolerance)
__device__ __forceinline__ float sigm_f(float x) {
    return __fdividef(1.0f, 1.0f + __expf(-x));
}
__device__ __forceinline__ float tanh_f(float x) {
    return __fdividef(2.0f, 1.0f + __expf(-2.0f * x)) - 1.0f;
}
__device__ __forceinline__ float sigm(float x) { return 1.0f / (1.0f + expf(-x)); }

// ---------------- mask init ----------------
__global__ void k_init(const unsigned int* __restrict__ em) {
    int idx = blockIdx.x * 256 + threadIdx.x;
    if (idx >= NROWS) return;
    int t = idx / MM, i = idx % MM;
    int b = i / 500, n = i % 500;
    d_maskf[idx] = em[(b * TT + t) * 500 + n] ? 1.0f : 0.0f;
}

// ---------------- column-scan sparse extraction (atomic-free, deterministic) ----------------
__global__ void k_extract(const float* __restrict__ adj) {
    int t = blockIdx.y;
    int i = blockIdx.x * 256 + threadIdx.x;
    __shared__ float msm[MM];
    for (int j = threadIdx.x; j < MM; j += 256) msm[j] = d_maskf[t * MM + j];
    __syncthreads();
    if (i >= MM) return;
    const float* a = adj + (size_t)t * MM * MM + i;   // column i
    unsigned short* list = d_nbr + (size_t)(t * MM + i) * CAP;
    int cnt = 0;
    #pragma unroll 8
    for (int j = 0; j < MM; j++) {
        float av = a[(size_t)j * MM];
        if (av != 0.0f && msm[j] != 0.0f) {
            if (cnt < CAP) list[cnt] = (unsigned short)j;
            cnt++;
        }
    }
    float mi = d_maskf[t * MM + i];
    d_cnt[t * MM + i] = (cnt < CAP ? cnt : CAP);
    d_dinv[t * MM + i] = (mi != 0.0f) ? rsqrtf((float)cnt + 1.0f) : 0.0f;
}

// ---------------- Z1 = dinv .* (x @ W1) ----------------
__global__ void k_z1(const float* __restrict__ pos, const float* __restrict__ W1) {
    int idx = blockIdx.x * 256 + threadIdx.x;
    if (idx >= NROWS * 128) return;
    int row = idx >> 7, c = idx & 127;
    float x0 = __ldg(&pos[(size_t)row * 2]);
    float x1 = __ldg(&pos[(size_t)row * 2 + 1]);
    d_bufA[idx] = d_dinv[row] * (x0 * __ldg(&W1[c]) + x1 * __ldg(&W1[128 + c]));
}

// ---------------- aggregation: out[i] = f( dinv[i]*(sum_nbr Z[j] + Z[i]) + bias ) ----------------
__global__ void k_agg(const float* __restrict__ Zin, const float* __restrict__ bias,
                      float* __restrict__ out, int mode) {
    int row = blockIdx.x;
    int f = threadIdx.x;
    int t = row / MM;
    size_t base = (size_t)t * MM;
    float acc = Zin[(size_t)row * 128 + f];
    int n = d_cnt[row];
    const unsigned short* lst = &d_nbr[(size_t)row * CAP];
    for (int idx = 0; idx < n; idx++) {
        int j = lst[idx];
        acc += Zin[(base + j) * 128 + f];
    }
    float v = d_dinv[row] * acc + __ldg(&bias[f]);
    if (mode == 0) out[(size_t)row * 128 + f] = fmaxf(v, 0.0f);
    else           out[(size_t)row * 128 + f] = v * d_maskf[row];
}

// ---------------- tiled GEMM, K=128 fixed, packed f32x2 ----------------
// mode 0 (Z2):    A row = r,                B = W2   [k][c],  epi: *dinv[r]
// mode 1 (gates): A row = (r%20)*2000+r/20, B = W_ih [c][k],  epi: + b_ih[c]+b_hh[c]
__global__ void __launch_bounds__(256)
k_gemm(const float* __restrict__ A, const float* __restrict__ B, float* __restrict__ C,
       const float* __restrict__ bia, const float* __restrict__ bib,
       int mode, int ncols) {
    extern __shared__ float sm[];
    float* As = sm;            // [64][128]
    float* Bs = sm + 64 * 128; // [128][130]
    int r0 = blockIdx.x * 64, c0 = blockIdx.y * 128;
    int tid = threadIdx.x;

    for (int i = tid; i < 64 * 32; i += 256) {
        int row = i / 32, k4 = i % 32;
        int gr = r0 + row;
        int arow = (mode == 1) ? ((gr % TT) * MM + gr / TT) : gr;
        ((float4*)As)[row * 32 + k4] = ((const float4*)A)[(size_t)arow * 32 + k4];
    }
    if (mode == 1) {
        for (int i = tid; i < 128 * 32; i += 256) {
            int c = i / 32, k4 = i % 32;
            float4 v = ((const float4*)B)[(size_t)(c0 + c) * 32 + k4];
            Bs[c * 130 + 4 * k4 + 0] = v.x; Bs[c * 130 + 4 * k4 + 1] = v.y;
            Bs[c * 130 + 4 * k4 + 2] = v.z; Bs[c * 130 + 4 * k4 + 3] = v.w;
        }
    } else {
        for (int i = tid; i < 128 * 32; i += 256) {
            int k = i / 32, c4 = i % 32;
            float4 v = ((const float4*)B)[(size_t)k * 32 + c4];
            Bs[(4 * c4 + 0) * 130 + k] = v.x; Bs[(4 * c4 + 1) * 130 + k] = v.y;
            Bs[(4 * c4 + 2) * 130 + k] = v.z; Bs[(4 * c4 + 3) * 130 + k] = v.w;
        }
    }
    __syncthreads();

    int tx = tid % 32, ty = tid / 32;
    unsigned long long acc[8][4];
    #pragma unroll
    for (int rr = 0; rr < 8; rr++)
        #pragma unroll
        for (int cc = 0; cc < 4; cc++) acc[rr][cc] = 0ull;

    const ulonglong2* As2 = (const ulonglong2*)As;
    #pragma unroll 4
    for (int k4 = 0; k4 < 32; k4++) {
        ulonglong2 a[8];
        #pragma unroll
        for (int rr = 0; rr < 8; rr++) a[rr] = As2[(ty * 8 + rr) * 32 + k4];
        #pragma unroll
        for (int cc = 0; cc < 4; cc++) {
            int c = tx + 32 * cc;
            const unsigned long long* bp = (const unsigned long long*)(Bs + c * 130 + 4 * k4);
            unsigned long long b0 = bp[0], b1 = bp[1];
            #pragma unroll
            for (int rr = 0; rr < 8; rr++) {
                FMA2(acc[rr][cc], a[rr].x, b0);
                FMA2(acc[rr][cc], a[rr].y, b1);
            }
        }
    }
    #pragma unroll
    for (int cc = 0; cc < 4; cc++) {
        int c = tx + 32 * cc;
        float bv = (mode == 1) ? (__ldg(&bia[c0 + c]) + __ldg(&bib[c0 + c])) : 0.0f;
        #pragma unroll
        for (int rr = 0; rr < 8; rr++) {
            int r = r0 + ty * 8 + rr;
            float lo, hi; UNPK(lo, hi, acc[rr][cc]);
            float v = lo + hi;
            if (mode == 1) v += bv;
            else           v *= d_dinv[r];
            C[(size_t)r * ncols + c0 + c] = v;
        }
    }
}

// ---------------- persistent LSTM: 20 blocks, 512 threads (1 gate/thread) ----------------
// W_hh[g][0:96) in 48 packed-ull registers, [96:128) in smem.
// Each thread applies its own gate nonlinearity BEFORE the barrier (distributed
// over 512 threads); post-barrier serial path = 4 LDS + c update + 1 tanh.
__global__ void __launch_bounds__(512, 1)
k_lstm(const float* __restrict__ Whh) {
    extern __shared__ float sm[];
    float* Wq  = sm;                 // [8][512] float4 : W_hh[g][96+4kq .. +3]
    float* hsm = sm + 8 * 512 * 4;   // 128
    float* gsm = hsm + 128;          // 512 (activated gates)
    int t = blockIdx.x, g = threadIdx.x;
    int quad = g >> 7;               // 0:i 1:f 2:g 3:o  (4-warp-uniform)

    unsigned long long w[48];
    const unsigned long long* wrow = (const unsigned long long*)(Whh + (size_t)g * 128);
    #pragma unroll
    for (int i = 0; i < 48; i++) w[i] = wrow[i];
    #pragma unroll
    for (int kq = 0; kq < 8; kq++)
        ((float4*)Wq)[kq * 512 + g] = __ldg((const float4*)(Whh + (size_t)g * 128 + 96 + 4 * kq));

    float c = 0.0f;
    if (g < 128) hsm[g] = 0.0f;
    __syncthreads();

    float nextg = d_gpre[(size_t)t * 512 + g];   // m = 0
    const ulonglong2* wq2 = (const ulonglong2*)Wq;
    for (int m = 0; m < MM; m++) {
        float gp = nextg;
        if (m < MM - 1) nextg = d_gpre[(size_t)((m + 1) * TT + t) * 512 + g];
        unsigned long long accA = 0ull, accB = 0ull;   // 2 chains
        const ulonglong2* h2 = (const ulonglong2*)hsm;
        #pragma unroll
        for (int j = 0; j < 24; j++) {            // k = 0..95, register weights
            ulonglong2 hv = h2[j];
            FMA2(accA, hv.x, w[2 * j]);
            FMA2(accB, hv.y, w[2 * j + 1]);
        }
        #pragma unroll
        for (int kq = 0; kq < 8; kq++) {          // k = 96..127, smem weights
            ulonglong2 hv = h2[24 + kq];
            ulonglong2 wv = wq2[kq * 512 + g];
            FMA2(accA, hv.x, wv.x);
            FMA2(accB, hv.y, wv.y);
        }
        float loA, hiA, loB, hiB;
        UNPK(loA, hiA, accA); UNPK(loB, hiB, accB);
        float part = (loA + hiA) + (loB + hiB) + gp;
        // distributed nonlinearity (pre-barrier, per-thread own value)
        gsm[g] = (quad == 2) ? tanh_f(part) : sigm_f(part);
        __syncthreads();
        if (g < 128) {
            float ig = gsm[g], fg = gsm[128 + g], gg = gsm[256 + g], og = gsm[384 + g];
            c = fg * c + ig * gg;
            float hn = og * tanh_f(c);
            hsm[g] = hn;
            d_lstm[(size_t)(m * TT + t) * 128 + g] = hn;
        }
        __syncthreads();
    }
}

// ---------------- fused FC1(relu)+FC2, 64 rows/block, packed f32x2 ----------------
__global__ void __launch_bounds__(256)
k_fc(const float* __restrict__ fc1w, const float* __restrict__ fc1b,
     const float* __restrict__ fc2w, const float* __restrict__ fc2b,
     float* __restrict__ out) {
    extern __shared__ float sm[];
    float* w1t = sm;                   // [64][130]
    float* w2t = w1t + 64 * 130;       // [32][66]
    float* xs  = w2t + 32 * 66;        // [64][128]
    float* mid = xs  + 64 * 128;       // [64][66]
    int tid = threadIdx.x;

    for (int i = tid; i < 128 * 64; i += 256) {
        int k = i >> 6, cc = i & 63;
        w1t[cc * 130 + k] = fc1w[i];
    }
    for (int i = tid; i < 64 * 32; i += 256) {
        int k = i >> 5, o = i & 31;
        w2t[o * 66 + k] = fc2w[i];
    }
    int rbase = blockIdx.x * 64;
    for (int i = tid; i < 64 * 32; i += 256)
        ((float4*)xs)[i] = ((const float4*)d_lstm)[(size_t)rbase * 32 + i];
    __syncthreads();

    int r = tid >> 2, q = tid & 3;
    {
        unsigned long long acc[16];
        #pragma unroll
        for (int j = 0; j < 16; j++) acc[j] = 0ull;
        const unsigned long long* xr = (const unsigned long long*)(xs + r * 128);
        #pragma unroll 4
        for (int kp = 0; kp < 64; kp++) {
            unsigned long long xv = xr[kp];
            #pragma unroll
            for (int j = 0; j < 16; j++)
                FMA2(acc[j], xv, *(const unsigned long long*)(w1t + (q * 16 + j) * 130 + 2 * kp));
        }
        #pragma unroll
        for (int j = 0; j < 16; j++) {
            float lo, hi; UNPK(lo, hi, acc[j]);
            int cc = q * 16 + j;
            mid[r * 66 + cc] = fmaxf(lo + hi + __ldg(&fc1b[cc]), 0.0f);
        }
    }
    __syncthreads();
    {
        unsigned long long acc[8];
        #pragma unroll
        for (int j = 0; j < 8; j++) acc[j] = 0ull;
        const unsigned long long* mr = (const unsigned long long*)(mid + r * 66);
        #pragma unroll 4
        for (int kp = 0; kp < 32; kp++) {
            unsigned long long mv = mr[kp];
            #pragma unroll
            for (int j = 0; j < 8; j++)
                FMA2(acc[j], mv, *(const unsigned long long*)(w2t + (q * 8 + j) * 66 + 2 * kp));
        }
        #pragma unroll
        for (int j = 0; j < 8; j++) {
            float lo, hi; UNPK(lo, hi, acc[j]);
            int o = q * 8 + j;
            out[(size_t)(rbase + r) * 32 + o] = lo + hi + __ldg(&fc2b[o]);
        }
    }
}

// ---------------- launch ----------------
extern "C" void kernel_launch(void* const* d_in, const int* in_sizes, int n_in,
                              void* d_out, int out_size) {
    const float* positions = (const float*)d_in[0];
    const float* adjacency = (const float*)d_in[1];
    const unsigned int* ego = (const unsigned int*)d_in[2];
    const float* W1   = (const float*)d_in[3];
    const float* b1   = (const float*)d_in[4];
    const float* W2   = (const float*)d_in[5];
    const float* b2   = (const float*)d_in[6];
    const float* W_ih = (const float*)d_in[7];
    const float* W_hh = (const float*)d_in[8];
    const float* b_ih = (const float*)d_in[9];
    const float* b_hh = (const float*)d_in[10];
    const float* fc1w = (const float*)d_in[11];
    const float* fc1b = (const float*)d_in[12];
    const float* fc2w = (const float*)d_in[13];
    const float* fc2b = (const float*)d_in[14];
    float* out = (float*)d_out;

    static const int GEMM_SMEM = (64 * 128 + 128 * 130) * 4;            // 99328
    static const int LSTM_SMEM = (8 * 512 * 4 + 128 + 512) * 4;         // 68096
    static const int FC_SMEM   = (64 * 130 + 32 * 66 + 64 * 128 + 64 * 66) * 4;  // 91392
    cudaFuncSetAttribute(k_gemm, cudaFuncAttributeMaxDynamicSharedMemorySize, GEMM_SMEM);
    cudaFuncSetAttribute(k_lstm, cudaFuncAttributeMaxDynamicSharedMemorySize, LSTM_SMEM);
    cudaFuncSetAttribute(k_fc,   cudaFuncAttributeMaxDynamicSharedMemorySize, FC_SMEM);

    float* bufA; cudaGetSymbolAddress((void**)&bufA, d_bufA);
    float* bufB; cudaGetSymbolAddress((void**)&bufB, d_bufB);
    float* gpre; cudaGetSymbolAddress((void**)&gpre, d_gpre);

    k_init<<<(NROWS + 255) / 256, 256>>>(ego);
    k_extract<<<dim3(8, TT), 256>>>(adjacency);
    k_z1<<<(NROWS * 128 + 255) / 256, 256>>>(positions, W1);
    k_agg<<<NROWS, 128>>>(bufA, b1, bufB, 0);                                   // h1
    k_gemm<<<dim3(625, 1), 256, GEMM_SMEM>>>(bufB, W2, bufA, 0, 0, 0, 128);     // Z2
    k_agg<<<NROWS, 128>>>(bufA, b2, bufB, 1);                                   // placeholder
    k_gemm<<<dim3(625, 4), 256, GEMM_SMEM>>>(bufB, W_ih, gpre, b_ih, b_hh, 1, 512);
    k_lstm<<<TT, 512, LSTM_SMEM>>>(W_hh);
    k_fc<<<625, 256, FC_SMEM>>>(fc1w, fc1b, fc2w, fc2b, out);
}

// round 7
// speedup vs baseline: 1.1452x; 1.0086x over previous
#include <cuda_runtime.h>
#include <math.h>

#define TT 20
#define MM 2000
#define NROWS (TT*MM)          // 40000, row index = t*MM + m
#define CAP 96

#define FMA2(d,a,b) asm("fma.rn.f32x2 %0,%1,%2,%0;" : "+l"(d) : "l"(a), "l"(b))
#define UNPK(lo,hi,v) asm("mov.b64 {%0,%1},%2;" : "=f"(lo), "=f"(hi) : "l"(v))

// ---------------- static scratch ----------------
__device__ float          d_maskf[NROWS];
__device__ int            d_cnt[NROWS];
__device__ float          d_dinv[NROWS];
__device__ unsigned short d_nbr[(size_t)NROWS * CAP];
__device__ float          d_bufA[(size_t)NROWS * 128];   // Z2
__device__ float          d_bufB[(size_t)NROWS * 128];   // h1 / placeholder
__device__ float          d_gpre[(size_t)NROWS * 512];   // [m*T+t][512]
__device__ float          d_lstm[(size_t)NROWS * 128];   // [m*T+t][128]

// fast nonlinearities: MUFU EX2 based, err ~1e-7 (vs 1e-3 tolerance)
__device__ __forceinline__ float sigm_f(float x) {
    return __fdividef(1.0f, 1.0f + __expf(-x));
}
__device__ __forceinline__ float tanh_f(float x) {
    return __fdividef(2.0f, 1.0f + __expf(-2.0f * x)) - 1.0f;
}

// ---------------- extraction + mask init (fused) ----------------
__global__ void k_extract(const float* __restrict__ adj, const unsigned int* __restrict__ em) {
    int t = blockIdx.y;
    int i = blockIdx.x * 256 + threadIdx.x;
    __shared__ float msm[MM];
    for (int j = threadIdx.x; j < MM; j += 256) {
        int b = j / 500, n = j % 500;
        float v = em[(b * TT + t) * 500 + n] ? 1.0f : 0.0f;
        msm[j] = v;
        if (blockIdx.x == 0) d_maskf[t * MM + j] = v;
    }
    __syncthreads();
    if (i >= MM) return;
    const float* a = adj + (size_t)t * MM * MM + i;   // column i
    unsigned short* list = d_nbr + (size_t)(t * MM + i) * CAP;
    int cnt = 0;
    #pragma unroll 8
    for (int j = 0; j < MM; j++) {
        float av = a[(size_t)j * MM];
        if (av != 0.0f && msm[j] != 0.0f) {
            if (cnt < CAP) list[cnt] = (unsigned short)j;
            cnt++;
        }
    }
    float mi = msm[i];
    d_cnt[t * MM + i] = (cnt < CAP ? cnt : CAP);
    d_dinv[t * MM + i] = (mi != 0.0f) ? rsqrtf((float)cnt + 1.0f) : 0.0f;
}

// ---------------- fused GCN1: h1 = relu( dinv_i * ((Σ dinv_j x_j) @ W1) + b1 ) ----------------
// W1 applied after the neighbor sum (linearity) -> only 2 scalars reduced per row.
__global__ void k_agg1(const float2* __restrict__ pos2, const float* __restrict__ W1,
                       const float* __restrict__ b1, float* __restrict__ out) {
    int row = blockIdx.x;
    int f = threadIdx.x;
    int t = row / MM;
    size_t base = (size_t)t * MM;
    float di = d_dinv[row];
    float2 xi = __ldg(&pos2[row]);
    float wx0 = di * xi.x, wx1 = di * xi.y;      // self term
    int n = d_cnt[row];
    const unsigned short* lst = &d_nbr[(size_t)row * CAP];
    for (int idx = 0; idx < n; idx++) {
        size_t j = base + lst[idx];
        float dj = __ldg(&d_dinv[j]);
        float2 xj = __ldg(&pos2[j]);
        wx0 += dj * xj.x;
        wx1 += dj * xj.y;
    }
    float v = di * (wx0 * __ldg(&W1[f]) + wx1 * __ldg(&W1[128 + f])) + __ldg(&b1[f]);
    out[(size_t)row * 128 + f] = fmaxf(v, 0.0f);
}

// ---------------- GCN2 aggregation: out = (dinv_i*(Σ Z2[j] + Z2[i]) + b2) * mask ----------------
__global__ void k_agg2(const float* __restrict__ Zin, const float* __restrict__ bias,
                       float* __restrict__ out) {
    int row = blockIdx.x;
    int f = threadIdx.x;
    int t = row / MM;
    size_t base = (size_t)t * MM;
    float acc = Zin[(size_t)row * 128 + f];
    int n = d_cnt[row];
    const unsigned short* lst = &d_nbr[(size_t)row * CAP];
    for (int idx = 0; idx < n; idx++) {
        int j = lst[idx];
        acc += Zin[(base + j) * 128 + f];
    }
    float v = d_dinv[row] * acc + __ldg(&bias[f]);
    out[(size_t)row * 128 + f] = v * d_maskf[row];
}

// ---------------- tiled GEMM, K=128 fixed, packed f32x2 ----------------
// mode 0 (Z2):    A row = r,                B = W2   [k][c],  epi: *dinv[r]
// mode 1 (gates): A row = (r%20)*2000+r/20, B = W_ih [c][k],  epi: + b_ih[c]+b_hh[c]
__global__ void __launch_bounds__(256)
k_gemm(const float* __restrict__ A, const float* __restrict__ B, float* __restrict__ C,
       const float* __restrict__ bia, const float* __restrict__ bib,
       int mode, int ncols) {
    extern __shared__ float sm[];
    float* As = sm;            // [64][128]
    float* Bs = sm + 64 * 128; // [128][130]
    int r0 = blockIdx.x * 64, c0 = blockIdx.y * 128;
    int tid = threadIdx.x;

    for (int i = tid; i < 64 * 32; i += 256) {
        int row = i / 32, k4 = i % 32;
        int gr = r0 + row;
        int arow = (mode == 1) ? ((gr % TT) * MM + gr / TT) : gr;
        ((float4*)As)[row * 32 + k4] = ((const float4*)A)[(size_t)arow * 32 + k4];
    }
    if (mode == 1) {
        for (int i = tid; i < 128 * 32; i += 256) {
            int c = i / 32, k4 = i % 32;
            float4 v = ((const float4*)B)[(size_t)(c0 + c) * 32 + k4];
            Bs[c * 130 + 4 * k4 + 0] = v.x; Bs[c * 130 + 4 * k4 + 1] = v.y;
            Bs[c * 130 + 4 * k4 + 2] = v.z; Bs[c * 130 + 4 * k4 + 3] = v.w;
        }
    } else {
        for (int i = tid; i < 128 * 32; i += 256) {
            int k = i / 32, c4 = i % 32;
            float4 v = ((const float4*)B)[(size_t)k * 32 + c4];
            Bs[(4 * c4 + 0) * 130 + k] = v.x; Bs[(4 * c4 + 1) * 130 + k] = v.y;
            Bs[(4 * c4 + 2) * 130 + k] = v.z; Bs[(4 * c4 + 3) * 130 + k] = v.w;
        }
    }
    __syncthreads();

    int tx = tid % 32, ty = tid / 32;
    unsigned long long acc[8][4];
    #pragma unroll
    for (int rr = 0; rr < 8; rr++)
        #pragma unroll
        for (int cc = 0; cc < 4; cc++) acc[rr][cc] = 0ull;

    const ulonglong2* As2 = (const ulonglong2*)As;
    #pragma unroll 4
    for (int k4 = 0; k4 < 32; k4++) {
        ulonglong2 a[8];
        #pragma unroll
        for (int rr = 0; rr < 8; rr++) a[rr] = As2[(ty * 8 + rr) * 32 + k4];
        #pragma unroll
        for (int cc = 0; cc < 4; cc++) {
            int c = tx + 32 * cc;
            const unsigned long long* bp = (const unsigned long long*)(Bs + c * 130 + 4 * k4);
            unsigned long long b0 = bp[0], b1 = bp[1];
            #pragma unroll
            for (int rr = 0; rr < 8; rr++) {
                FMA2(acc[rr][cc], a[rr].x, b0);
                FMA2(acc[rr][cc], a[rr].y, b1);
            }
        }
    }
    #pragma unroll
    for (int cc = 0; cc < 4; cc++) {
        int c = tx + 32 * cc;
        float bv = (mode == 1) ? (__ldg(&bia[c0 + c]) + __ldg(&bib[c0 + c])) : 0.0f;
        #pragma unroll
        for (int rr = 0; rr < 8; rr++) {
            int r = r0 + ty * 8 + rr;
            float lo, hi; UNPK(lo, hi, acc[rr][cc]);
            float v = lo + hi;
            if (mode == 1) v += bv;
            else           v *= d_dinv[r];
            C[(size_t)r * ncols + c0 + c] = v;
        }
    }
}

// ---------------- persistent LSTM: 20 blocks, 512 threads ----------------
// Thread g -> (unit j = g>>2, gate q = g&3): a unit's 4 gates sit in adjacent
// lanes, so gate exchange is 3x shfl_down (no gsm round-trip). h double-buffered
// in smem -> ONE __syncthreads per step. Weight row = q*128+j: [0:96) in 48 ull
// registers, [96:128) in smem. Branchless single-MUFU-path nonlinearity.
__global__ void __launch_bounds__(512, 1)
k_lstm(const float* __restrict__ Whh) {
    extern __shared__ float sm[];
    float* Wq  = sm;                 // [8][512] float4 : W_hh[row][96+4kq .. +3]
    float* hsm = sm + 8 * 512 * 4;   // [2][128] double-buffered h
    int t = blockIdx.x, g = threadIdx.x;
    int q = g & 3, j = g >> 2;
    int grow = q * 128 + j;          // gate row in [512]

    unsigned long long w[48];
    const unsigned long long* wrow = (const unsigned long long*)(Whh + (size_t)grow * 128);
    #pragma unroll
    for (int i = 0; i < 48; i++) w[i] = wrow[i];
    #pragma unroll
    for (int kq = 0; kq < 8; kq++)
        ((float4*)Wq)[kq * 512 + g] = __ldg((const float4*)(Whh + (size_t)grow * 128 + 96 + 4 * kq));

    float c = 0.0f;
    if (g < 128) hsm[g] = 0.0f;      // buffer 0
    __syncthreads();

    float nextg = d_gpre[(size_t)t * 512 + grow];   // m = 0
    const ulonglong2* wq2 = (const ulonglong2*)Wq;
    for (int m = 0; m < MM; m++) {
        float gp = nextg;
        if (m < MM - 1) nextg = d_gpre[(size_t)((m + 1) * TT + t) * 512 + grow];
        const ulonglong2* h2 = (const ulonglong2*)(hsm + (m & 1) * 128);
        unsigned long long accA = 0ull, accB = 0ull;
        #pragma unroll
        for (int jj = 0; jj < 24; jj++) {         // k = 0..95, register weights
            ulonglong2 hv = h2[jj];
            FMA2(accA, hv.x, w[2 * jj]);
            FMA2(accB, hv.y, w[2 * jj + 1]);
        }
        #pragma unroll
        for (int kq = 0; kq < 8; kq++) {          // k = 96..127, smem weights
            ulonglong2 hv = h2[24 + kq];
            ulonglong2 wv = wq2[kq * 512 + g];
            FMA2(accA, hv.x, wv.x);
            FMA2(accB, hv.y, wv.y);
        }
        float loA, hiA, loB, hiB;
        UNPK(loA, hiA, accA); UNPK(loB, hiB, accB);
        float part = (loA + hiA) + (loB + hiB) + gp;
        // branchless nonlinearity: tanh(x) = 2*sigm(2x)-1
        float xin = (q == 2) ? 2.0f * part : part;
        float s = sigm_f(xin);
        float act = (q == 2) ? fmaf(2.0f, s, -1.0f) : s;
        // gate exchange within warp: lanes q=0 gather f,g,o from lanes +1,+2,+3
        float a1 = __shfl_down_sync(0xffffffffu, act, 1);
        float a2 = __shfl_down_sync(0xffffffffu, act, 2);
        float a3 = __shfl_down_sync(0xffffffffu, act, 3);
        if (q == 0) {
            c = a1 * c + act * a2;                // f*c + i*g
            float hn = a3 * tanh_f(c);            // o*tanh(c)
            hsm[((m & 1) ^ 1) * 128 + j] = hn;    // write buffer
            d_lstm[(size_t)(m * TT + t) * 128 + j] = hn;
        }
        __syncthreads();
    }
}

// ---------------- fused FC1(relu)+FC2, 64 rows/block, packed f32x2 ----------------
__global__ void __launch_bounds__(256)
k_fc(const float* __restrict__ fc1w, const float* __restrict__ fc1b,
     const float* __restrict__ fc2w, const float* __restrict__ fc2b,
     float* __restrict__ out) {
    extern __shared__ float sm[];
    float* w1t = sm;                   // [64][130]
    float* w2t = w1t + 64 * 130;       // [32][66]
    float* xs  = w2t + 32 * 66;        // [64][128]
    float* mid = xs  + 64 * 128;       // [64][66]
    int tid = threadIdx.x;

    for (int i = tid; i < 128 * 64; i += 256) {
        int k = i >> 6, cc = i & 63;
        w1t[cc * 130 + k] = fc1w[i];
    }
    for (int i = tid; i < 64 * 32; i += 256) {
        int k = i >> 5, o = i & 31;
        w2t[o * 66 + k] = fc2w[i];
    }
    int rbase = blockIdx.x * 64;
    for (int i = tid; i < 64 * 32; i += 256)
        ((float4*)xs)[i] = ((const float4*)d_lstm)[(size_t)rbase * 32 + i];
    __syncthreads();

    int r = tid >> 2, q = tid & 3;
    {
        unsigned long long acc[16];
        #pragma unroll
        for (int j = 0; j < 16; j++) acc[j] = 0ull;
        const unsigned long long* xr = (const unsigned long long*)(xs + r * 128);
        #pragma unroll 4
        for (int kp = 0; kp < 64; kp++) {
            unsigned long long xv = xr[kp];
            #pragma unroll
            for (int j = 0; j < 16; j++)
                FMA2(acc[j], xv, *(const unsigned long long*)(w1t + (q * 16 + j) * 130 + 2 * kp));
        }
        #pragma unroll
        for (int j = 0; j < 16; j++) {
            float lo, hi; UNPK(lo, hi, acc[j]);
            int cc = q * 16 + j;
            mid[r * 66 + cc] = fmaxf(lo + hi + __ldg(&fc1b[cc]), 0.0f);
        }
    }
    __syncthreads();
    {
        unsigned long long acc[8];
        #pragma unroll
        for (int j = 0; j < 8; j++) acc[j] = 0ull;
        const unsigned long long* mr = (const unsigned long long*)(mid + r * 66);
        #pragma unroll 4
        for (int kp = 0; kp < 32; kp++) {
            unsigned long long mv = mr[kp];
            #pragma unroll
            for (int j = 0; j < 8; j++)
                FMA2(acc[j], mv, *(const unsigned long long*)(w2t + (q * 8 + j) * 66 + 2 * kp));
        }
        #pragma unroll
        for (int j = 0; j < 8; j++) {
            float lo, hi; UNPK(lo, hi, acc[j]);
            int o = q * 8 + j;
            out[(size_t)(rbase + r) * 32 + o] = lo + hi + __ldg(&fc2b[o]);
        }
    }
}

// ---------------- launch ----------------
extern "C" void kernel_launch(void* const* d_in, const int* in_sizes, int n_in,
                              void* d_out, int out_size) {
    const float* positions = (const float*)d_in[0];
    const float* adjacency = (const float*)d_in[1];
    const unsigned int* ego = (const unsigned int*)d_in[2];
    const float* W1   = (const float*)d_in[3];
    const float* b1   = (const float*)d_in[4];
    const float* W2   = (const float*)d_in[5];
    const float* b2   = (const float*)d_in[6];
    const float* W_ih = (const float*)d_in[7];
    const float* W_hh = (const float*)d_in[8];
    const float* b_ih = (const float*)d_in[9];
    const float* b_hh = (const float*)d_in[10];
    const float* fc1w = (const float*)d_in[11];
    const float* fc1b = (const float*)d_in[12];
    const float* fc2w = (const float*)d_in[13];
    const float* fc2b = (const float*)d_in[14];
    float* out = (float*)d_out;

    static const int GEMM_SMEM = (64 * 128 + 128 * 130) * 4;            // 99328
    static const int LSTM_SMEM = (8 * 512 * 4 + 256) * 4;               // 66560
    static const int FC_SMEM   = (64 * 130 + 32 * 66 + 64 * 128 + 64 * 66) * 4;  // 91392
    cudaFuncSetAttribute(k_gemm, cudaFuncAttributeMaxDynamicSharedMemorySize, GEMM_SMEM);
    cudaFuncSetAttribute(k_lstm, cudaFuncAttributeMaxDynamicSharedMemorySize, LSTM_SMEM);
    cudaFuncSetAttribute(k_fc,   cudaFuncAttributeMaxDynamicSharedMemorySize, FC_SMEM);

    float* bufA; cudaGetSymbolAddress((void**)&bufA, d_bufA);
    float* bufB; cudaGetSymbolAddress((void**)&bufB, d_bufB);
    float* gpre; cudaGetSymbolAddress((void**)&gpre, d_gpre);

    // launch index:                                                       idx
    k_extract<<<dim3(8, TT), 256>>>(adjacency, ego);                    // 0
    k_agg1<<<NROWS, 128>>>((const float2*)positions, W1, b1, bufB);     // 1  h1
    k_gemm<<<dim3(625, 1), 256, GEMM_SMEM>>>(bufB, W2, bufA, 0, 0, 0, 128);      // 2  Z2
    k_agg2<<<NROWS, 128>>>(bufA, b2, bufB);                             // 3  placeholder
    k_gemm<<<dim3(625, 4), 256, GEMM_SMEM>>>(bufB, W_ih, gpre, b_ih, b_hh, 1, 512); // 4
    k_lstm<<<TT, 512, LSTM_SMEM>>>(W_hh);                               // 5  <- ncu -s 5
    k_fc<<<625, 256, FC_SMEM>>>(fc1w, fc1b, fc2w, fc2b, out);           // 6
}